// round 9
// baseline (speedup 1.0000x reference)
#include <cuda_runtime.h>
#include <cuda_fp16.h>
#include <math.h>
#include <cstdint>

#define BATCH 128
#define NPT   500
#define NROWS (BATCH*NPT)

typedef unsigned long long ull;

// ---------------- scratch (static; no allocation) ----------------
__device__ __align__(256) __half g_actP[52428800];
__device__ __align__(256) __half g_actQ[52428800];
__device__ __align__(256) __half g_wH[742528];
__device__ __align__(256) __half g_tail1[NROWS * 8];
__device__ __align__(256) __half g_tail2[128000 * 8];
__device__ __align__(256) int g_idx1[BATCH * 500];
__device__ __align__(256) int g_idx2[BATCH * 1000];

// weight arena offsets (elements, K padded to mult of 8)
#define OFF_W2   0
#define OFF_PC1  16384
#define OFF_W3   81920
#define OFF_W4   149504
#define OFF_PC2  247808
#define OFF_W5   395264
#define OFF_W6   545792

// ---------------- helpers ----------------
__device__ __forceinline__ uint32_t smem_u32(const void* p) {
    uint32_t a;
    asm("{ .reg .u64 t; cvta.to.shared.u64 t, %1; cvt.u32.u64 %0, t; }" : "=r"(a) : "l"(p));
    return a;
}
__device__ __forceinline__ void cpa16(uint32_t dst, const void* src, int sz) {
    asm volatile("cp.async.cg.shared.global [%0], [%1], 16, %2;"
        :: "r"(dst), "l"(src), "r"(sz) : "memory");
}
__device__ __forceinline__ void ldm_x4(uint32_t* r, uint32_t addr) {
    asm volatile("ldmatrix.sync.aligned.m8n8.x4.shared.b16 {%0,%1,%2,%3}, [%4];"
        : "=r"(r[0]), "=r"(r[1]), "=r"(r[2]), "=r"(r[3]) : "r"(addr));
}
__device__ __forceinline__ void mma_f16(float* d, const uint32_t* a, uint32_t b0, uint32_t b1) {
    asm volatile("mma.sync.aligned.m16n8k16.row.col.f32.f16.f16.f32 "
        "{%0,%1,%2,%3}, {%4,%5,%6,%7}, {%8,%9}, {%0,%1,%2,%3};"
        : "+f"(d[0]), "+f"(d[1]), "+f"(d[2]), "+f"(d[3])
        : "r"(a[0]), "r"(a[1]), "r"(a[2]), "r"(a[3]), "r"(b0), "r"(b1));
}

// ---------------- fp16 HMMA GEMM, templated on CTA N-tile ----------------
// C = relu?( sum_k A[m,k]*W[n,k] + bias[n] ). Warp tile 64 x (BN/4).
// BN=128: 8 warps 2Mx4N, 2 CTAs/SM. BN=256: 8 warps 2Mx4N (64x64), 1 CTA/SM.
// Optional inline row-gather: rowIdx (absolute A rows, cached in smem) + 8-half tail.
// mode: 0 fp32 C, 1 fp16 C, 2 fused per-1000-row-batch column max into Cf.
template<int BN>
__device__ __forceinline__ void fill_t(
    const __half* __restrict__ A, const __half* __restrict__ W,
    const int* __restrict__ sIdx, int useIdx, const __half* __restrict__ tailA,
    int N, int K, int lda, int row0, int col0, int s, int nst, uint32_t sb, int tid)
{
    const int STG = 16384 + BN * 128;
    if (s < nst) {
        int k0 = s << 6;
        uint32_t base = sb + (uint32_t)(s % 3) * STG;
#pragma unroll
        for (int i = 0; i < 4; i++) {            // A: 128 rows x 8 chunks
            int g = (i << 8) + tid;
            int r = g >> 3, c = g & 7;
            int kg = k0 + (c << 3);
            int ok = (kg < K) ? 16 : 0;
            uint32_t d = base + ((uint32_t)r << 7) + (((uint32_t)(c ^ (r & 7))) << 4);
            const __half* src;
            if (useIdx) {
                int sr = sIdx[r];
                src = (kg < lda) ? (A + (size_t)sr * lda + kg)
                                 : (tailA + (size_t)(row0 + r) * 8);
            } else {
                src = A + (size_t)(row0 + r) * lda + kg;
            }
            cpa16(d, src, ok);
        }
#pragma unroll
        for (int i = 0; i < BN / 32; i++) {      // W: BN rows x 8 chunks
            int g = (i << 8) + tid;
            int r = g >> 3, c = g & 7;
            int kg = k0 + (c << 3);
            int ok = (kg < K && (col0 + r) < N) ? 16 : 0;
            uint32_t d = base + 16384 + ((uint32_t)r << 7) + (((uint32_t)(c ^ (r & 7))) << 4);
            cpa16(d, W + (size_t)(col0 + r) * K + kg, ok);
        }
    }
    asm volatile("cp.async.commit_group;" ::: "memory");
}

template<int BN>
__global__ void __launch_bounds__(256, BN == 128 ? 2 : 1)
gemm_t(const __half* __restrict__ A, const __half* __restrict__ W,
       const float* __restrict__ bias,
       float* __restrict__ Cf, __half* __restrict__ Ch,
       const int* __restrict__ rowIdx, const __half* __restrict__ tailA,
       int M, int N, int K, int lda, int relu, int mode)
{
    const int STG = 16384 + BN * 128;
    const int WN = BN / 4;         // warp N extent
    const int NP = BN / 64;        // ldm_x4 pairs per warp (2 or 4)
    extern __shared__ char smem[];
    int* sIdx = (int*)(smem + 3 * STG);
    uint32_t sb = smem_u32(smem);
    int tid = threadIdx.x, lane = tid & 31, wid = tid >> 5;
    int warp_m = wid & 1;
    int warp_n = wid >> 1;
    int row0 = blockIdx.y << 7;
    int col0 = blockIdx.x * BN;
    int nst = (K + 63) >> 6;
    int useIdx = (rowIdx != nullptr);

    if (useIdx && tid < 128) sIdx[tid] = rowIdx[row0 + tid];
    __syncthreads();

    float acc[4][2 * NP][4];
#pragma unroll
    for (int a = 0; a < 4; a++)
#pragma unroll
        for (int b = 0; b < 2 * NP; b++)
#pragma unroll
            for (int c = 0; c < 4; c++) acc[a][b][c] = 0.f;

    fill_t<BN>(A, W, sIdx, useIdx, tailA, N, K, lda, row0, col0, 0, nst, sb, tid);
    fill_t<BN>(A, W, sIdx, useIdx, tailA, N, K, lda, row0, col0, 1, nst, sb, tid);

    int a_row = warp_m * 64 + (lane & 15);
    int a_sel = lane >> 4;
    int b_row4 = warp_n * WN + ((lane >> 4) << 3) + (lane & 7);
    int b_ksel = (lane >> 3) & 1;

    for (int s = 0; s < nst; s++) {
        asm volatile("cp.async.wait_group 1;" ::: "memory");
        __syncthreads();
        uint32_t base = sb + (uint32_t)(s % 3) * STG;
        int kr = K - (s << 6);
        int kcnt = (kr + 15) >> 4; if (kcnt > 4) kcnt = 4;
        for (int ks = 0; ks < kcnt; ks++) {
            uint32_t Fa[4][4];
            int ch_a = (ks << 1) + a_sel;
#pragma unroll
            for (int mi = 0; mi < 4; mi++) {
                int rr = a_row + mi * 16;
                ldm_x4(Fa[mi], base + ((uint32_t)rr << 7) + (((uint32_t)(ch_a ^ (rr & 7))) << 4));
            }
            int ch_b = (ks << 1) + b_ksel;
#pragma unroll
            for (int np = 0; np < NP; np++) {
                int nr = b_row4 + np * 16;
                uint32_t B4[4];
                ldm_x4(B4, base + 16384 + ((uint32_t)nr << 7)
                           + (((uint32_t)(ch_b ^ (nr & 7))) << 4));
#pragma unroll
                for (int mi = 0; mi < 4; mi++) {
                    mma_f16(acc[mi][np * 2],     Fa[mi], B4[0], B4[1]);
                    mma_f16(acc[mi][np * 2 + 1], Fa[mi], B4[2], B4[3]);
                }
            }
        }
        fill_t<BN>(A, W, sIdx, useIdx, tailA, N, K, lda, row0, col0, s + 2, nst, sb, tid);
    }

    int er = row0 + warp_m * 64 + (lane >> 2);
    int ec = col0 + warp_n * WN + ((lane & 3) << 1);
    if (mode != 2) {
#pragma unroll
        for (int ni = 0; ni < 2 * NP; ni++) {
            int c = ec + ni * 8;
            float b0 = __ldg(bias + c), b1 = __ldg(bias + c + 1);
#pragma unroll
            for (int mi = 0; mi < 4; mi++) {
                int r = er + mi * 16;
                float v00 = acc[mi][ni][0] + b0, v01 = acc[mi][ni][1] + b1;
                float v10 = acc[mi][ni][2] + b0, v11 = acc[mi][ni][3] + b1;
                if (relu) {
                    v00 = fmaxf(v00, 0.f); v01 = fmaxf(v01, 0.f);
                    v10 = fmaxf(v10, 0.f); v11 = fmaxf(v11, 0.f);
                }
                if (mode == 0) {
                    *(float2*)(Cf + (size_t)r * N + c)       = make_float2(v00, v01);
                    *(float2*)(Cf + (size_t)(r + 8) * N + c) = make_float2(v10, v11);
                } else {
                    *(__half2*)(Ch + (size_t)r * N + c)       = __floats2half2_rn(v00, v01);
                    *(__half2*)(Ch + (size_t)(r + 8) * N + c) = __floats2half2_rn(v10, v11);
                }
            }
        }
    } else {
        // fused per-batch (1000 rows) column max -> Cf[batch][N] via atomicMax (values >= 0)
        int bat0 = row0 / 1000;
        int cut = (bat0 + 1) * 1000;
        bool has2 = (row0 + 127 >= cut);
        int* outI = (int*)Cf;
#pragma unroll
        for (int ni = 0; ni < 2 * NP; ni++) {
            int c = ec + ni * 8;
            float b0 = __ldg(bias + c), b1 = __ldg(bias + c + 1);
            float s00 = 0.f, s01 = 0.f, s10 = 0.f, s11 = 0.f;
#pragma unroll
            for (int mi = 0; mi < 4; mi++) {
                int r = er + mi * 16;
                float v00 = fmaxf(acc[mi][ni][0] + b0, 0.f);
                float v01 = fmaxf(acc[mi][ni][1] + b1, 0.f);
                float v10 = fmaxf(acc[mi][ni][2] + b0, 0.f);
                float v11 = fmaxf(acc[mi][ni][3] + b1, 0.f);
                if (r < cut)     { s00 = fmaxf(s00, v00); s01 = fmaxf(s01, v01); }
                else             { s10 = fmaxf(s10, v00); s11 = fmaxf(s11, v01); }
                if (r + 8 < cut) { s00 = fmaxf(s00, v10); s01 = fmaxf(s01, v11); }
                else             { s10 = fmaxf(s10, v10); s11 = fmaxf(s11, v11); }
            }
#pragma unroll
            for (int d = 4; d <= 16; d <<= 1) {
                s00 = fmaxf(s00, __shfl_xor_sync(0xffffffffu, s00, d));
                s01 = fmaxf(s01, __shfl_xor_sync(0xffffffffu, s01, d));
                s10 = fmaxf(s10, __shfl_xor_sync(0xffffffffu, s10, d));
                s11 = fmaxf(s11, __shfl_xor_sync(0xffffffffu, s11, d));
            }
            if ((lane >> 2) == 0) {
                atomicMax(outI + bat0 * N + c,     __float_as_int(s00));
                atomicMax(outI + bat0 * N + c + 1, __float_as_int(s01));
                if (has2) {
                    atomicMax(outI + (bat0 + 1) * N + c,     __float_as_int(s10));
                    atomicMax(outI + (bat0 + 1) * N + c + 1, __float_as_int(s11));
                }
            }
        }
    }
}

static const int SMEM128 = 3 * (16384 + 128 * 128) + 512;
static const int SMEM256 = 3 * (16384 + 256 * 128) + 512;

// ---------------- out init ----------------
__global__ void init_out(float* __restrict__ out) {
    int t = blockIdx.x * 256 + threadIdx.x;
    if (t < BATCH * 512) out[t] = 0.f;
}

// ---------------- weight pack (fp32 -> fp16, pad K) ----------------
__global__ void pack_w(const float* __restrict__ w2, const float* __restrict__ pc1,
                       const float* __restrict__ w3, const float* __restrict__ w4,
                       const float* __restrict__ pc2, const float* __restrict__ w5,
                       const float* __restrict__ w6) {
    int t = blockIdx.x * 256 + threadIdx.x;
    if (t >= 742400) return;
    float v;
    if (t < 81920) {
        v = (t < 16384) ? w2[t] : pc1[t - 16384];
    } else if (t < 149504) {
        int i = t - 81920; int r = i / 264, c = i - r * 264;
        v = (c < 259) ? w3[r * 259 + c] : 0.f;
    } else if (t < 247808) {
        v = w4[t - 149504];
    } else if (t < 395264) {
        v = pc2[t - 247808];
    } else if (t < 545792) {
        int i = t - 395264; int r = i / 392, c = i - r * 392;
        v = (c < 387) ? w5[r * 387 + c] : 0.f;
    } else {
        v = w6[t - 545792];
    }
    g_wH[t] = __float2half_rn(v);
}

// ---------------- fused conf + concat + first linear -> fp16 ----------------
__global__ void point_mlp1(const float* __restrict__ x,
                           const float* __restrict__ confW, const float* __restrict__ confb,
                           const float* __restrict__ w1, const float* __restrict__ b1) {
    int t = blockIdx.x * 256 + threadIdx.x;
    if (t >= NROWS * 4) return;
    int p = t >> 2, g = t & 3;
    float x0 = x[p * 3], x1 = x[p * 3 + 1], x2 = x[p * 3 + 2];
    float s = confW[0] * x0 + confW[1] * x1 + confW[2] * x2 + confb[0];
    float conf = 1.f / (1.f + expf(-s));
    const float* wr = w1 + (g * 16) * 4;
    __half h[16];
#pragma unroll
    for (int r = 0; r < 16; r++) {
        float a = __ldg(b1 + g * 16 + r)
                + __ldg(wr + r * 4 + 0) * conf + __ldg(wr + r * 4 + 1) * x0
                + __ldg(wr + r * 4 + 2) * x1   + __ldg(wr + r * 4 + 3) * x2;
        h[r] = __float2half_rn(fmaxf(a, 0.f));
    }
    size_t o = (size_t)p * 64 + g * 16;
    *(uint4*)(g_actP + o)     = *(uint4*)h;
    *(uint4*)(g_actP + o + 8) = *(uint4*)(h + 8);
}

// ---------------- farthest point sampling (bitwise-matches XLA); ABSOLUTE indices ----------------
__global__ void fps_run(const float* __restrict__ x, const int* __restrict__ far0,
                        int* __restrict__ idxout, int npoint) {
    __shared__ float sxx[512], sxy[512], sxz[512];
    int b = blockIdx.x;
    int* out = idxout + b * npoint;
    int abs0 = b * NPT;
    int far = far0[b];
    const float* xb = x + (size_t)b * NPT * 3;
    int lane = threadIdx.x;

    float px[16], py[16], pz[16], dist[16];
#pragma unroll
    for (int j = 0; j < 16; j++) {
        int p = j * 32 + lane;
        if (p < NPT) {
            px[j] = xb[p * 3]; py[j] = xb[p * 3 + 1]; pz[j] = xb[p * 3 + 2];
            dist[j] = 1e10f;
            sxx[p] = px[j]; sxy[p] = py[j]; sxz[p] = pz[j];
        } else {
            px[j] = 0.f; py[j] = 0.f; pz[j] = 0.f;
            dist[j] = -1.0f;
        }
    }
    __syncwarp();

    for (int t = 0; t < npoint; t++) {
        if (lane == 0) out[t] = abs0 + far;
        if (t + 1 == npoint) break;
        float cx = sxx[far], cy = sxy[far], cz = sxz[far];
        float nd[16];
#pragma unroll
        for (int j = 0; j < 16; j++) {
            float dx = __fsub_rn(px[j], cx);
            float dy = __fsub_rn(py[j], cy);
            float dz = __fsub_rn(pz[j], cz);
            float d  = __fadd_rn(__fadd_rn(__fmul_rn(dx, dx), __fmul_rn(dy, dy)),
                                 __fmul_rn(dz, dz));
            nd[j] = fminf(dist[j], d);
            dist[j] = nd[j];
        }
        float m[8];
#pragma unroll
        for (int j = 0; j < 8; j++) m[j] = fmaxf(nd[2 * j], nd[2 * j + 1]);
#pragma unroll
        for (int j = 0; j < 4; j++) m[j] = fmaxf(m[j], m[j + 4]);
        m[0] = fmaxf(m[0], m[2]); m[1] = fmaxf(m[1], m[3]);
        float best = fmaxf(m[0], m[1]);
        unsigned mb = __reduce_max_sync(0xffffffffu, __float_as_uint(best));
        unsigned c[16];
#pragma unroll
        for (int j = 0; j < 16; j++)
            c[j] = (__float_as_uint(nd[j]) == mb) ? (unsigned)(j * 32 + lane) : 0xffffffffu;
#pragma unroll
        for (int j = 0; j < 8; j++) c[j] = min(c[j], c[j + 8]);
#pragma unroll
        for (int j = 0; j < 4; j++) c[j] = min(c[j], c[j + 4]);
        c[0] = min(c[0], c[2]); c[1] = min(c[1], c[3]);
        far = (int)__reduce_min_sync(0xffffffffu, min(c[0], c[1]));
    }
}

// ---------------- tail builder: tail[r] = [x(idx[r]).xyz as fp16, 0 x5] ----------------
__global__ void make_tail(const float* __restrict__ x, const int* __restrict__ idx,
                          __half* __restrict__ tail, int n) {
    int r = blockIdx.x * 256 + threadIdx.x;
    if (r >= n) return;
    const float* xp = x + (size_t)idx[r] * 3;
    __half h[8];
#pragma unroll
    for (int j = 0; j < 8; j++) h[j] = __float2half(0.f);
#pragma unroll
    for (int j = 0; j < 3; j++) h[j] = __float2half_rn(xp[j]);
    *(uint4*)(tail + (size_t)r * 8) = *(uint4*)h;
}

// ---------------- launch ----------------
extern "C" void kernel_launch(void* const* d_in, const int* in_sizes, int n_in,
                              void* d_out, int out_size) {
    const float* x     = (const float*)d_in[0];
    const float* confW = (const float*)d_in[1];
    const float* confb = (const float*)d_in[2];
    const float* w1    = (const float*)d_in[3];
    const float* b1    = (const float*)d_in[4];
    const float* w2    = (const float*)d_in[5];
    const float* b2    = (const float*)d_in[6];
    const float* pc1W  = (const float*)d_in[7];
    const float* pc1b  = (const float*)d_in[8];
    const float* w3    = (const float*)d_in[9];
    const float* b3    = (const float*)d_in[10];
    const float* w4    = (const float*)d_in[11];
    const float* b4    = (const float*)d_in[12];
    const float* pc2W  = (const float*)d_in[13];
    const float* pc2b  = (const float*)d_in[14];
    const float* w5    = (const float*)d_in[15];
    const float* b5    = (const float*)d_in[16];
    const float* w6    = (const float*)d_in[17];
    const float* b6    = (const float*)d_in[18];
    const int* far1    = (const int*)d_in[20];
    const int* far2    = (const int*)d_in[21];
    float* out = (float*)d_out;

    __half *actP, *actQ, *wH, *tail1, *tail2;
    int *idx1, *idx2;
    cudaGetSymbolAddress((void**)&actP, g_actP);
    cudaGetSymbolAddress((void**)&actQ, g_actQ);
    cudaGetSymbolAddress((void**)&wH,   g_wH);
    cudaGetSymbolAddress((void**)&tail1, g_tail1);
    cudaGetSymbolAddress((void**)&tail2, g_tail2);
    cudaGetSymbolAddress((void**)&idx1, g_idx1);
    cudaGetSymbolAddress((void**)&idx2, g_idx2);

    cudaFuncSetAttribute(gemm_t<128>, cudaFuncAttributeMaxDynamicSharedMemorySize, SMEM128);
    cudaFuncSetAttribute(gemm_t<256>, cudaFuncAttributeMaxDynamicSharedMemorySize, SMEM256);

    static cudaStream_t s1 = nullptr, s2 = nullptr;
    static cudaEvent_t evA = nullptr, ev1 = nullptr, ev2 = nullptr;
    if (s1 == nullptr) {
        cudaStreamCreateWithFlags(&s1, cudaStreamNonBlocking);
        cudaStreamCreateWithFlags(&s2, cudaStreamNonBlocking);
        cudaEventCreateWithFlags(&evA, cudaEventDisableTiming);
        cudaEventCreateWithFlags(&ev1, cudaEventDisableTiming);
        cudaEventCreateWithFlags(&ev2, cudaEventDisableTiming);
    }

    init_out<<<(BATCH * 512 + 255) / 256, 256>>>(out);

    // fork: FPS1+tail1 on s1, FPS2+tail2 on s2
    cudaEventRecord(evA, 0);
    cudaStreamWaitEvent(s1, evA, 0);
    cudaStreamWaitEvent(s2, evA, 0);
    fps_run<<<BATCH, 32, 0, s1>>>(x, far1, idx1, 500);
    make_tail<<<(NROWS + 255) / 256, 256, 0, s1>>>(x, idx1, tail1, NROWS);
    cudaEventRecord(ev1, s1);
    fps_run<<<BATCH, 32, 0, s2>>>(x, far2, idx2, 1000);
    make_tail<<<(128000 + 255) / 256, 256, 0, s2>>>(x, idx2, tail2, 128000);
    cudaEventRecord(ev2, s2);

    pack_w<<<(742400 + 255) / 256, 256>>>(w2, pc1W, w3, w4, pc2W, w5, w6);
    point_mlp1<<<(NROWS * 4 + 255) / 256, 256>>>(x, confW, confb, w1, b1);

    // l2: (64000x256, K=64), relu
    gemm_t<256><<<dim3(1, 500), 256, SMEM256>>>(actP, wH + OFF_W2, b2,
        nullptr, actQ, nullptr, nullptr, NROWS, 256, 64, 64, 1, 1);
    // l3: (64000x256, K=256)
    gemm_t<256><<<dim3(1, 500), 256, SMEM256>>>(actQ, wH + OFF_PC1, pc1b,
        nullptr, actP, nullptr, nullptr, NROWS, 256, 256, 256, 0, 1);

    // join idx1; l4 gathers A rows inline from l3 output (lda=256, K=264 w/ tail)
    cudaStreamWaitEvent(0, ev1, 0);
    gemm_t<256><<<dim3(1, 500), 256, SMEM256>>>(actP, wH + OFF_W3, b3,
        nullptr, actQ, idx1, tail1, NROWS, 256, 264, 256, 1, 1);
    // l5: (64000x384, K=256), relu
    gemm_t<128><<<dim3(3, 500), 256, SMEM128>>>(actQ, wH + OFF_W4, b4,
        nullptr, actP, nullptr, nullptr, NROWS, 384, 256, 256, 1, 1);
    // l6: (64000x384, K=384)
    gemm_t<128><<<dim3(3, 500), 256, SMEM128>>>(actP, wH + OFF_PC2, pc2b,
        nullptr, actQ, nullptr, nullptr, NROWS, 384, 384, 384, 0, 1);

    // join idx2; l7 gathers A rows inline from l6 output (lda=384, K=392 w/ tail)
    cudaStreamWaitEvent(0, ev2, 0);
    gemm_t<128><<<dim3(3, 1000), 256, SMEM128>>>(actQ, wH + OFF_W5, b5,
        nullptr, actP, idx2, tail2, 128000, 384, 392, 384, 1, 1);
    // l8: (128000x512, K=384), relu, FUSED max-pool -> out
    gemm_t<256><<<dim3(2, 1000), 256, SMEM256>>>(actP, wH + OFF_W6, b6,
        out, nullptr, nullptr, nullptr, 128000, 512, 384, 384, 1, 2);
}

// round 10
// speedup vs baseline: 1.1745x; 1.1745x over previous
#include <cuda_runtime.h>
#include <cuda_fp16.h>
#include <math.h>
#include <cstdint>

#define BATCH 128
#define NPT   500
#define NROWS (BATCH*NPT)

typedef unsigned long long ull;

// ---------------- scratch (static; no allocation) ----------------
__device__ __align__(256) __half g_actP[52428800];
__device__ __align__(256) __half g_actQ[52428800];
__device__ __align__(256) __half g_wH[742528];
__device__ __align__(256) __half g_tail1[NROWS * 8];
__device__ __align__(256) __half g_tail2[128000 * 8];
__device__ __align__(256) int g_idx1[BATCH * 500];
__device__ __align__(256) int g_idx2[BATCH * 1000];

// weight arena offsets (elements, K padded to mult of 8)
#define OFF_W2   0
#define OFF_PC1  16384
#define OFF_W3   81920
#define OFF_W4   149504
#define OFF_PC2  247808
#define OFF_W5   395264
#define OFF_W6   545792

// ---------------- helpers ----------------
__device__ __forceinline__ uint32_t smem_u32(const void* p) {
    uint32_t a;
    asm("{ .reg .u64 t; cvta.to.shared.u64 t, %1; cvt.u32.u64 %0, t; }" : "=r"(a) : "l"(p));
    return a;
}
__device__ __forceinline__ void cpa16(uint32_t dst, const void* src, int sz) {
    asm volatile("cp.async.cg.shared.global [%0], [%1], 16, %2;"
        :: "r"(dst), "l"(src), "r"(sz) : "memory");
}
__device__ __forceinline__ void ldm_x4(uint32_t* r, uint32_t addr) {
    asm volatile("ldmatrix.sync.aligned.m8n8.x4.shared.b16 {%0,%1,%2,%3}, [%4];"
        : "=r"(r[0]), "=r"(r[1]), "=r"(r[2]), "=r"(r[3]) : "r"(addr));
}
__device__ __forceinline__ void mma_f16(float* d, const uint32_t* a, uint32_t b0, uint32_t b1) {
    asm volatile("mma.sync.aligned.m16n8k16.row.col.f32.f16.f16.f32 "
        "{%0,%1,%2,%3}, {%4,%5,%6,%7}, {%8,%9}, {%0,%1,%2,%3};"
        : "+f"(d[0]), "+f"(d[1]), "+f"(d[2]), "+f"(d[3])
        : "r"(a[0]), "r"(a[1]), "r"(a[2]), "r"(a[3]), "r"(b0), "r"(b1));
}

// ---------------- fp16 HMMA GEMM (R8-proven BN=128 tile + optional inline row-gather) --------
// C = relu?( sum_k A[m,k]*W[n,k] + bias[n] ). CTA 128x128x64, 8 warps 2Mx4N, warp 64x32.
// 3-stage cp.async (32KB/stage), 2 CTAs/SM. rowIdx: absolute A rows (smem-cached) + 8-half tail
// for K beyond lda. mode: 0 fp32 C, 1 fp16 C, 2 fused per-1000-row-batch column max.
#define NSTG 3
#define STG 32768
static const int GEMM_SMEM = NSTG * STG + 512;

__device__ __forceinline__ void g_fill(
    const __half* __restrict__ A, const __half* __restrict__ W,
    const int* __restrict__ sIdx, int useIdx, const __half* __restrict__ tailA,
    int K, int lda, int row0, int col0, int s, int nst, uint32_t sb, int tid)
{
    if (s < nst) {
        int k0 = s << 6;
        uint32_t base = sb + (uint32_t)(s % NSTG) * STG;
#pragma unroll
        for (int i = 0; i < 4; i++) {
            int g = (i << 8) + tid;
            int r = g >> 3, c = g & 7;
            int kg = k0 + (c << 3);
            int ok = (kg < K) ? 16 : 0;
            uint32_t d = base + ((uint32_t)r << 7) + (((uint32_t)(c ^ (r & 7))) << 4);
            const __half* srcA;
            if (useIdx) {
                int sr = sIdx[r];
                srcA = (kg < lda) ? (A + (size_t)sr * lda + kg)
                                  : (tailA + (size_t)(row0 + r) * 8);
            } else {
                srcA = A + (size_t)(row0 + r) * lda + kg;
            }
            cpa16(d,         srcA, ok);
            cpa16(d + 16384, W + (size_t)(col0 + r) * K + kg, ok);
        }
    }
    asm volatile("cp.async.commit_group;" ::: "memory");
}

__global__ void __launch_bounds__(256, 2)
gemm_f16(const __half* __restrict__ A, const __half* __restrict__ W,
         const float* __restrict__ bias,
         float* __restrict__ Cf, __half* __restrict__ Ch,
         const int* __restrict__ rowIdx, const __half* __restrict__ tailA,
         int M, int N, int K, int lda, int relu, int mode)
{
    extern __shared__ char smem[];
    int* sIdx = (int*)(smem + NSTG * STG);
    uint32_t sb = smem_u32(smem);
    int tid = threadIdx.x, lane = tid & 31, wid = tid >> 5;
    int warp_m = wid & 1;
    int warp_n = wid >> 1;
    int row0 = blockIdx.y << 7;
    int col0 = blockIdx.x << 7;
    int nst = (K + 63) >> 6;
    int useIdx = (rowIdx != nullptr);

    if (useIdx && tid < 128) sIdx[tid] = rowIdx[row0 + tid];
    __syncthreads();

    float acc[4][4][4];
#pragma unroll
    for (int a = 0; a < 4; a++)
#pragma unroll
        for (int b = 0; b < 4; b++)
#pragma unroll
            for (int c = 0; c < 4; c++) acc[a][b][c] = 0.f;

    g_fill(A, W, sIdx, useIdx, tailA, K, lda, row0, col0, 0, nst, sb, tid);
    g_fill(A, W, sIdx, useIdx, tailA, K, lda, row0, col0, 1, nst, sb, tid);

    int a_row = warp_m * 64 + (lane & 15);
    int a_sel = lane >> 4;
    int b_row4 = warp_n * 32 + ((lane >> 4) << 3) + (lane & 7);
    int b_ksel = (lane >> 3) & 1;

    for (int s = 0; s < nst; s++) {
        asm volatile("cp.async.wait_group 1;" ::: "memory");
        __syncthreads();
        uint32_t base = sb + (uint32_t)(s % NSTG) * STG;
        int kr = K - (s << 6);
        int kcnt = (kr + 15) >> 4; if (kcnt > 4) kcnt = 4;
        for (int ks = 0; ks < kcnt; ks++) {
            uint32_t Fa[4][4];
            int ch_a = (ks << 1) + a_sel;
#pragma unroll
            for (int mi = 0; mi < 4; mi++) {
                int rr = a_row + mi * 16;
                ldm_x4(Fa[mi], base + ((uint32_t)rr << 7) + (((uint32_t)(ch_a ^ (rr & 7))) << 4));
            }
            int ch_b = (ks << 1) + b_ksel;
#pragma unroll
            for (int np = 0; np < 2; np++) {
                int nr = b_row4 + np * 16;
                uint32_t B4[4];
                ldm_x4(B4, base + 16384 + ((uint32_t)nr << 7)
                           + (((uint32_t)(ch_b ^ (nr & 7))) << 4));
#pragma unroll
                for (int mi = 0; mi < 4; mi++) {
                    mma_f16(acc[mi][np * 2],     Fa[mi], B4[0], B4[1]);
                    mma_f16(acc[mi][np * 2 + 1], Fa[mi], B4[2], B4[3]);
                }
            }
        }
        g_fill(A, W, sIdx, useIdx, tailA, K, lda, row0, col0, s + 2, nst, sb, tid);
    }

    int er = row0 + warp_m * 64 + (lane >> 2);
    int ec = col0 + warp_n * 32 + ((lane & 3) << 1);
    if (mode != 2) {
#pragma unroll
        for (int ni = 0; ni < 4; ni++) {
            int c = ec + ni * 8;
            float b0 = __ldg(bias + c), b1 = __ldg(bias + c + 1);
#pragma unroll
            for (int mi = 0; mi < 4; mi++) {
                int r = er + mi * 16;
                float v00 = acc[mi][ni][0] + b0, v01 = acc[mi][ni][1] + b1;
                float v10 = acc[mi][ni][2] + b0, v11 = acc[mi][ni][3] + b1;
                if (relu) {
                    v00 = fmaxf(v00, 0.f); v01 = fmaxf(v01, 0.f);
                    v10 = fmaxf(v10, 0.f); v11 = fmaxf(v11, 0.f);
                }
                if (mode == 0) {
                    *(float2*)(Cf + (size_t)r * N + c)       = make_float2(v00, v01);
                    *(float2*)(Cf + (size_t)(r + 8) * N + c) = make_float2(v10, v11);
                } else {
                    *(__half2*)(Ch + (size_t)r * N + c)       = __floats2half2_rn(v00, v01);
                    *(__half2*)(Ch + (size_t)(r + 8) * N + c) = __floats2half2_rn(v10, v11);
                }
            }
        }
    } else {
        int bat0 = row0 / 1000;
        int cut = (bat0 + 1) * 1000;
        bool has2 = (row0 + 127 >= cut);
        int* outI = (int*)Cf;
#pragma unroll
        for (int ni = 0; ni < 4; ni++) {
            int c = ec + ni * 8;
            float b0 = __ldg(bias + c), b1 = __ldg(bias + c + 1);
            float s00 = 0.f, s01 = 0.f, s10 = 0.f, s11 = 0.f;
#pragma unroll
            for (int mi = 0; mi < 4; mi++) {
                int r = er + mi * 16;
                float v00 = fmaxf(acc[mi][ni][0] + b0, 0.f);
                float v01 = fmaxf(acc[mi][ni][1] + b1, 0.f);
                float v10 = fmaxf(acc[mi][ni][2] + b0, 0.f);
                float v11 = fmaxf(acc[mi][ni][3] + b1, 0.f);
                if (r < cut)     { s00 = fmaxf(s00, v00); s01 = fmaxf(s01, v01); }
                else             { s10 = fmaxf(s10, v00); s11 = fmaxf(s11, v01); }
                if (r + 8 < cut) { s00 = fmaxf(s00, v10); s01 = fmaxf(s01, v11); }
                else             { s10 = fmaxf(s10, v10); s11 = fmaxf(s11, v11); }
            }
#pragma unroll
            for (int d = 4; d <= 16; d <<= 1) {
                s00 = fmaxf(s00, __shfl_xor_sync(0xffffffffu, s00, d));
                s01 = fmaxf(s01, __shfl_xor_sync(0xffffffffu, s01, d));
                s10 = fmaxf(s10, __shfl_xor_sync(0xffffffffu, s10, d));
                s11 = fmaxf(s11, __shfl_xor_sync(0xffffffffu, s11, d));
            }
            if ((lane >> 2) == 0) {
                atomicMax(outI + bat0 * N + c,     __float_as_int(s00));
                atomicMax(outI + bat0 * N + c + 1, __float_as_int(s01));
                if (has2) {
                    atomicMax(outI + (bat0 + 1) * N + c,     __float_as_int(s10));
                    atomicMax(outI + (bat0 + 1) * N + c + 1, __float_as_int(s11));
                }
            }
        }
    }
}

// ---------------- out init ----------------
__global__ void init_out(float* __restrict__ out) {
    int t = blockIdx.x * 256 + threadIdx.x;
    if (t < BATCH * 512) out[t] = 0.f;
}

// ---------------- weight pack (fp32 -> fp16, pad K) ----------------
__global__ void pack_w(const float* __restrict__ w2, const float* __restrict__ pc1,
                       const float* __restrict__ w3, const float* __restrict__ w4,
                       const float* __restrict__ pc2, const float* __restrict__ w5,
                       const float* __restrict__ w6) {
    int t = blockIdx.x * 256 + threadIdx.x;
    if (t >= 742400) return;
    float v;
    if (t < 81920) {
        v = (t < 16384) ? w2[t] : pc1[t - 16384];
    } else if (t < 149504) {
        int i = t - 81920; int r = i / 264, c = i - r * 264;
        v = (c < 259) ? w3[r * 259 + c] : 0.f;
    } else if (t < 247808) {
        v = w4[t - 149504];
    } else if (t < 395264) {
        v = pc2[t - 247808];
    } else if (t < 545792) {
        int i = t - 395264; int r = i / 392, c = i - r * 392;
        v = (c < 387) ? w5[r * 387 + c] : 0.f;
    } else {
        v = w6[t - 545792];
    }
    g_wH[t] = __float2half_rn(v);
}

// ---------------- fused conf + concat + first linear -> fp16 ----------------
__global__ void point_mlp1(const float* __restrict__ x,
                           const float* __restrict__ confW, const float* __restrict__ confb,
                           const float* __restrict__ w1, const float* __restrict__ b1) {
    int t = blockIdx.x * 256 + threadIdx.x;
    if (t >= NROWS * 4) return;
    int p = t >> 2, g = t & 3;
    float x0 = x[p * 3], x1 = x[p * 3 + 1], x2 = x[p * 3 + 2];
    float s = confW[0] * x0 + confW[1] * x1 + confW[2] * x2 + confb[0];
    float conf = 1.f / (1.f + expf(-s));
    const float* wr = w1 + (g * 16) * 4;
    __half h[16];
#pragma unroll
    for (int r = 0; r < 16; r++) {
        float a = __ldg(b1 + g * 16 + r)
                + __ldg(wr + r * 4 + 0) * conf + __ldg(wr + r * 4 + 1) * x0
                + __ldg(wr + r * 4 + 2) * x1   + __ldg(wr + r * 4 + 3) * x2;
        h[r] = __float2half_rn(fmaxf(a, 0.f));
    }
    size_t o = (size_t)p * 64 + g * 16;
    *(uint4*)(g_actP + o)     = *(uint4*)h;
    *(uint4*)(g_actP + o + 8) = *(uint4*)(h + 8);
}

// ---------------- farthest point sampling: 2 warps/batch, exact XLA arithmetic ----------------
// Thread tid owns points p = j*64 + tid (j=0..7). Per-iter: warp-local argmax (bits,min-idx),
// cross-warp combine via parity-double-buffered smem + one barrier. Emits ABSOLUTE indices.
__global__ void fps_run(const float* __restrict__ x, const int* __restrict__ far0,
                        int* __restrict__ idxout, int npoint) {
    __shared__ float sxx[512], sxy[512], sxz[512];
    __shared__ unsigned cmb[2][2], cix[2][2];
    int b = blockIdx.x;
    int* out = idxout + b * npoint;
    int abs0 = b * NPT;
    int far = far0[b];
    const float* xb = x + (size_t)b * NPT * 3;
    int tid = threadIdx.x;
    int w = tid >> 5;

    float px[8], py[8], pz[8], dist[8];
#pragma unroll
    for (int j = 0; j < 8; j++) {
        int p = j * 64 + tid;
        if (p < NPT) {
            px[j] = xb[p * 3]; py[j] = xb[p * 3 + 1]; pz[j] = xb[p * 3 + 2];
            dist[j] = 1e10f;
            sxx[p] = px[j]; sxy[p] = py[j]; sxz[p] = pz[j];
        } else {
            px[j] = 0.f; py[j] = 0.f; pz[j] = 0.f;
            dist[j] = -1.0f;   // pad: never selected (valid dists >= 0)
        }
    }
    __syncthreads();

    for (int t = 0; t < npoint; t++) {
        if (tid == 0) out[t] = abs0 + far;
        if (t + 1 == npoint) break;
        float cx = sxx[far], cy = sxy[far], cz = sxz[far];
        float nd[8];
#pragma unroll
        for (int j = 0; j < 8; j++) {         // exact unfused ops: bitwise-match XLA
            float dx = __fsub_rn(px[j], cx);
            float dy = __fsub_rn(py[j], cy);
            float dz = __fsub_rn(pz[j], cz);
            float d  = __fadd_rn(__fadd_rn(__fmul_rn(dx, dx), __fmul_rn(dy, dy)),
                                 __fmul_rn(dz, dz));
            nd[j] = fminf(dist[j], d);
            dist[j] = nd[j];
        }
        // warp-local max (bits; valid dists >= 0 so unsigned order == float order)
        float m[4];
#pragma unroll
        for (int j = 0; j < 4; j++) m[j] = fmaxf(nd[2 * j], nd[2 * j + 1]);
        m[0] = fmaxf(m[0], m[2]); m[1] = fmaxf(m[1], m[3]);
        float best = fmaxf(m[0], m[1]);
        unsigned mb = __reduce_max_sync(0xffffffffu, __float_as_uint(best));
        unsigned c[8];
#pragma unroll
        for (int j = 0; j < 8; j++)
            c[j] = (__float_as_uint(nd[j]) == mb) ? (unsigned)(j * 64 + tid) : 0xffffffffu;
#pragma unroll
        for (int j = 0; j < 4; j++) c[j] = min(c[j], c[j + 4]);
        c[0] = min(c[0], c[2]); c[1] = min(c[1], c[3]);
        unsigned cw = __reduce_min_sync(0xffffffffu, min(c[0], c[1]));
        int sl = t & 1;
        if ((tid & 31) == 0) { cmb[w][sl] = mb; cix[w][sl] = cw; }
        __syncthreads();
        unsigned m0 = cmb[0][sl], m1 = cmb[1][sl];
        unsigned fm = m0 > m1 ? m0 : m1;
        unsigned i0 = (m0 == fm) ? cix[0][sl] : 0xffffffffu;
        unsigned i1 = (m1 == fm) ? cix[1][sl] : 0xffffffffu;
        far = (int)min(i0, i1);
    }
}

// ---------------- tail builder: tail[r] = [x(idx[r]).xyz as fp16, 0 x5] ----------------
__global__ void make_tail(const float* __restrict__ x, const int* __restrict__ idx,
                          __half* __restrict__ tail, int n) {
    int r = blockIdx.x * 256 + threadIdx.x;
    if (r >= n) return;
    const float* xp = x + (size_t)idx[r] * 3;
    __half h[8];
#pragma unroll
    for (int j = 0; j < 8; j++) h[j] = __float2half(0.f);
#pragma unroll
    for (int j = 0; j < 3; j++) h[j] = __float2half_rn(xp[j]);
    *(uint4*)(tail + (size_t)r * 8) = *(uint4*)h;
}

// ---------------- launch ----------------
extern "C" void kernel_launch(void* const* d_in, const int* in_sizes, int n_in,
                              void* d_out, int out_size) {
    const float* x     = (const float*)d_in[0];
    const float* confW = (const float*)d_in[1];
    const float* confb = (const float*)d_in[2];
    const float* w1    = (const float*)d_in[3];
    const float* b1    = (const float*)d_in[4];
    const float* w2    = (const float*)d_in[5];
    const float* b2    = (const float*)d_in[6];
    const float* pc1W  = (const float*)d_in[7];
    const float* pc1b  = (const float*)d_in[8];
    const float* w3    = (const float*)d_in[9];
    const float* b3    = (const float*)d_in[10];
    const float* w4    = (const float*)d_in[11];
    const float* b4    = (const float*)d_in[12];
    const float* pc2W  = (const float*)d_in[13];
    const float* pc2b  = (const float*)d_in[14];
    const float* w5    = (const float*)d_in[15];
    const float* b5    = (const float*)d_in[16];
    const float* w6    = (const float*)d_in[17];
    const float* b6    = (const float*)d_in[18];
    const int* far1    = (const int*)d_in[20];
    const int* far2    = (const int*)d_in[21];
    float* out = (float*)d_out;

    __half *actP, *actQ, *wH, *tail1, *tail2;
    int *idx1, *idx2;
    cudaGetSymbolAddress((void**)&actP, g_actP);
    cudaGetSymbolAddress((void**)&actQ, g_actQ);
    cudaGetSymbolAddress((void**)&wH,   g_wH);
    cudaGetSymbolAddress((void**)&tail1, g_tail1);
    cudaGetSymbolAddress((void**)&tail2, g_tail2);
    cudaGetSymbolAddress((void**)&idx1, g_idx1);
    cudaGetSymbolAddress((void**)&idx2, g_idx2);

    cudaFuncSetAttribute(gemm_f16, cudaFuncAttributeMaxDynamicSharedMemorySize, GEMM_SMEM);

    static cudaStream_t s1 = nullptr, s2 = nullptr;
    static cudaEvent_t evA = nullptr, ev1 = nullptr, ev2 = nullptr;
    if (s1 == nullptr) {
        cudaStreamCreateWithFlags(&s1, cudaStreamNonBlocking);
        cudaStreamCreateWithFlags(&s2, cudaStreamNonBlocking);
        cudaEventCreateWithFlags(&evA, cudaEventDisableTiming);
        cudaEventCreateWithFlags(&ev1, cudaEventDisableTiming);
        cudaEventCreateWithFlags(&ev2, cudaEventDisableTiming);
    }

    init_out<<<(BATCH * 512 + 255) / 256, 256>>>(out);

    // fork: FPS1+tail1 on s1, FPS2+tail2 on s2
    cudaEventRecord(evA, 0);
    cudaStreamWaitEvent(s1, evA, 0);
    cudaStreamWaitEvent(s2, evA, 0);
    fps_run<<<BATCH, 64, 0, s1>>>(x, far1, idx1, 500);
    make_tail<<<(NROWS + 255) / 256, 256, 0, s1>>>(x, idx1, tail1, NROWS);
    cudaEventRecord(ev1, s1);
    fps_run<<<BATCH, 64, 0, s2>>>(x, far2, idx2, 1000);
    make_tail<<<(128000 + 255) / 256, 256, 0, s2>>>(x, idx2, tail2, 128000);
    cudaEventRecord(ev2, s2);

    pack_w<<<(742400 + 255) / 256, 256>>>(w2, pc1W, w3, w4, pc2W, w5, w6);
    point_mlp1<<<(NROWS * 4 + 255) / 256, 256>>>(x, confW, confb, w1, b1);

    // l2: (64000x256, K=64), relu        actP -> actQ
    gemm_f16<<<dim3(2, 500), 256, GEMM_SMEM>>>(actP, wH + OFF_W2, b2,
        nullptr, actQ, nullptr, nullptr, NROWS, 256, 64, 64, 1, 1);
    // l3: (64000x256, K=256)             actQ -> actP
    gemm_f16<<<dim3(2, 500), 256, GEMM_SMEM>>>(actQ, wH + OFF_PC1, pc1b,
        nullptr, actP, nullptr, nullptr, NROWS, 256, 256, 256, 0, 1);

    // join idx1; l4 inline-gathers A rows from l3 output (lda=256, K=264 w/ tail)
    cudaStreamWaitEvent(0, ev1, 0);
    gemm_f16<<<dim3(2, 500), 256, GEMM_SMEM>>>(actP, wH + OFF_W3, b3,
        nullptr, actQ, idx1, tail1, NROWS, 256, 264, 256, 1, 1);
    // l5: (64000x384, K=256), relu       actQ -> actP
    gemm_f16<<<dim3(3, 500), 256, GEMM_SMEM>>>(actQ, wH + OFF_W4, b4,
        nullptr, actP, nullptr, nullptr, NROWS, 384, 256, 256, 1, 1);
    // l6: (64000x384, K=384)             actP -> actQ
    gemm_f16<<<dim3(3, 500), 256, GEMM_SMEM>>>(actP, wH + OFF_PC2, pc2b,
        nullptr, actQ, nullptr, nullptr, NROWS, 384, 384, 384, 0, 1);

    // join idx2; l7 inline-gathers A rows from l6 output (lda=384, K=392 w/ tail)
    cudaStreamWaitEvent(0, ev2, 0);
    gemm_f16<<<dim3(3, 1000), 256, GEMM_SMEM>>>(actQ, wH + OFF_W5, b5,
        nullptr, actP, idx2, tail2, 128000, 384, 392, 384, 1, 1);
    // l8: (128000x512, K=384), relu, FUSED max-pool -> out
    gemm_f16<<<dim3(4, 1000), 256, GEMM_SMEM>>>(actP, wH + OFF_W6, b6,
        out, nullptr, nullptr, nullptr, 128000, 512, 384, 384, 1, 2);
}

// round 11
// speedup vs baseline: 1.3812x; 1.1760x over previous
#include <cuda_runtime.h>
#include <cuda_fp16.h>
#include <math.h>
#include <cstdint>

#define BATCH 128
#define NPT   500
#define NROWS (BATCH*NPT)

typedef unsigned long long ull;

// ---------------- scratch (static; no allocation) ----------------
__device__ __align__(256) __half g_actP[52428800];
__device__ __align__(256) __half g_actQ[52428800];
__device__ __align__(256) __half g_wH[742528];
__device__ __align__(256) __half g_tail1[NROWS * 8];
__device__ __align__(256) __half g_tail2[128000 * 8];
__device__ __align__(256) int g_idx1[BATCH * 500];
__device__ __align__(256) int g_idx2[BATCH * 1000];

// weight arena offsets (elements, K padded to mult of 8)
#define OFF_W2   0
#define OFF_PC1  16384
#define OFF_W3   81920
#define OFF_W4   149504
#define OFF_PC2  247808
#define OFF_W5   395264
#define OFF_W6   545792

// ---------------- helpers ----------------
__device__ __forceinline__ uint32_t smem_u32(const void* p) {
    uint32_t a;
    asm("{ .reg .u64 t; cvta.to.shared.u64 t, %1; cvt.u32.u64 %0, t; }" : "=r"(a) : "l"(p));
    return a;
}
__device__ __forceinline__ void cpa16(uint32_t dst, const void* src, int sz) {
    asm volatile("cp.async.cg.shared.global [%0], [%1], 16, %2;"
        :: "r"(dst), "l"(src), "r"(sz) : "memory");
}
__device__ __forceinline__ void ldm_x4(uint32_t* r, uint32_t addr) {
    asm volatile("ldmatrix.sync.aligned.m8n8.x4.shared.b16 {%0,%1,%2,%3}, [%4];"
        : "=r"(r[0]), "=r"(r[1]), "=r"(r[2]), "=r"(r[3]) : "r"(addr));
}
__device__ __forceinline__ void mma_f16(float* d, const uint32_t* a, uint32_t b0, uint32_t b1) {
    asm volatile("mma.sync.aligned.m16n8k16.row.col.f32.f16.f16.f32 "
        "{%0,%1,%2,%3}, {%4,%5,%6,%7}, {%8,%9}, {%0,%1,%2,%3};"
        : "+f"(d[0]), "+f"(d[1]), "+f"(d[2]), "+f"(d[3])
        : "r"(a[0]), "r"(a[1]), "r"(a[2]), "r"(a[3]), "r"(b0), "r"(b1));
}

// ---------------- fp16 HMMA GEMM (R8-proven BN=128 tile + optional inline row-gather) --------
// C = relu?( sum_k A[m,k]*W[n,k] + bias[n] ). CTA 128x128x64, 8 warps 2Mx4N, warp 64x32.
// 3-stage cp.async (32KB/stage), 2 CTAs/SM. rowIdx: absolute A rows (smem-cached) + 8-half tail
// for K beyond lda. mode: 0 fp32 C, 1 fp16 C, 2 fused per-1000-row-batch column max.
#define NSTG 3
#define STG 32768
static const int GEMM_SMEM = NSTG * STG + 512;

__device__ __forceinline__ void g_fill(
    const __half* __restrict__ A, const __half* __restrict__ W,
    const int* __restrict__ sIdx, int useIdx, const __half* __restrict__ tailA,
    int K, int lda, int row0, int col0, int s, int nst, uint32_t sb, int tid)
{
    if (s < nst) {
        int k0 = s << 6;
        uint32_t base = sb + (uint32_t)(s % NSTG) * STG;
#pragma unroll
        for (int i = 0; i < 4; i++) {
            int g = (i << 8) + tid;
            int r = g >> 3, c = g & 7;
            int kg = k0 + (c << 3);
            int ok = (kg < K) ? 16 : 0;
            uint32_t d = base + ((uint32_t)r << 7) + (((uint32_t)(c ^ (r & 7))) << 4);
            const __half* srcA;
            if (useIdx) {
                int sr = sIdx[r];
                srcA = (kg < lda) ? (A + (size_t)sr * lda + kg)
                                  : (tailA + (size_t)(row0 + r) * 8);
            } else {
                srcA = A + (size_t)(row0 + r) * lda + kg;
            }
            cpa16(d,         srcA, ok);
            cpa16(d + 16384, W + (size_t)(col0 + r) * K + kg, ok);
        }
    }
    asm volatile("cp.async.commit_group;" ::: "memory");
}

__global__ void __launch_bounds__(256, 2)
gemm_f16(const __half* __restrict__ A, const __half* __restrict__ W,
         const float* __restrict__ bias,
         float* __restrict__ Cf, __half* __restrict__ Ch,
         const int* __restrict__ rowIdx, const __half* __restrict__ tailA,
         int M, int N, int K, int lda, int relu, int mode)
{
    extern __shared__ char smem[];
    int* sIdx = (int*)(smem + NSTG * STG);
    uint32_t sb = smem_u32(smem);
    int tid = threadIdx.x, lane = tid & 31, wid = tid >> 5;
    int warp_m = wid & 1;
    int warp_n = wid >> 1;
    int row0 = blockIdx.y << 7;
    int col0 = blockIdx.x << 7;
    int nst = (K + 63) >> 6;
    int useIdx = (rowIdx != nullptr);

    if (useIdx && tid < 128) sIdx[tid] = rowIdx[row0 + tid];
    __syncthreads();

    float acc[4][4][4];
#pragma unroll
    for (int a = 0; a < 4; a++)
#pragma unroll
        for (int b = 0; b < 4; b++)
#pragma unroll
            for (int c = 0; c < 4; c++) acc[a][b][c] = 0.f;

    g_fill(A, W, sIdx, useIdx, tailA, K, lda, row0, col0, 0, nst, sb, tid);
    g_fill(A, W, sIdx, useIdx, tailA, K, lda, row0, col0, 1, nst, sb, tid);

    int a_row = warp_m * 64 + (lane & 15);
    int a_sel = lane >> 4;
    int b_row4 = warp_n * 32 + ((lane >> 4) << 3) + (lane & 7);
    int b_ksel = (lane >> 3) & 1;

    for (int s = 0; s < nst; s++) {
        asm volatile("cp.async.wait_group 1;" ::: "memory");
        __syncthreads();
        uint32_t base = sb + (uint32_t)(s % NSTG) * STG;
        int kr = K - (s << 6);
        int kcnt = (kr + 15) >> 4; if (kcnt > 4) kcnt = 4;
        for (int ks = 0; ks < kcnt; ks++) {
            uint32_t Fa[4][4];
            int ch_a = (ks << 1) + a_sel;
#pragma unroll
            for (int mi = 0; mi < 4; mi++) {
                int rr = a_row + mi * 16;
                ldm_x4(Fa[mi], base + ((uint32_t)rr << 7) + (((uint32_t)(ch_a ^ (rr & 7))) << 4));
            }
            int ch_b = (ks << 1) + b_ksel;
#pragma unroll
            for (int np = 0; np < 2; np++) {
                int nr = b_row4 + np * 16;
                uint32_t B4[4];
                ldm_x4(B4, base + 16384 + ((uint32_t)nr << 7)
                           + (((uint32_t)(ch_b ^ (nr & 7))) << 4));
#pragma unroll
                for (int mi = 0; mi < 4; mi++) {
                    mma_f16(acc[mi][np * 2],     Fa[mi], B4[0], B4[1]);
                    mma_f16(acc[mi][np * 2 + 1], Fa[mi], B4[2], B4[3]);
                }
            }
        }
        g_fill(A, W, sIdx, useIdx, tailA, K, lda, row0, col0, s + 2, nst, sb, tid);
    }

    int er = row0 + warp_m * 64 + (lane >> 2);
    int ec = col0 + warp_n * 32 + ((lane & 3) << 1);
    if (mode != 2) {
#pragma unroll
        for (int ni = 0; ni < 4; ni++) {
            int c = ec + ni * 8;
            float b0 = __ldg(bias + c), b1 = __ldg(bias + c + 1);
#pragma unroll
            for (int mi = 0; mi < 4; mi++) {
                int r = er + mi * 16;
                float v00 = acc[mi][ni][0] + b0, v01 = acc[mi][ni][1] + b1;
                float v10 = acc[mi][ni][2] + b0, v11 = acc[mi][ni][3] + b1;
                if (relu) {
                    v00 = fmaxf(v00, 0.f); v01 = fmaxf(v01, 0.f);
                    v10 = fmaxf(v10, 0.f); v11 = fmaxf(v11, 0.f);
                }
                if (mode == 0) {
                    *(float2*)(Cf + (size_t)r * N + c)       = make_float2(v00, v01);
                    *(float2*)(Cf + (size_t)(r + 8) * N + c) = make_float2(v10, v11);
                } else {
                    *(__half2*)(Ch + (size_t)r * N + c)       = __floats2half2_rn(v00, v01);
                    *(__half2*)(Ch + (size_t)(r + 8) * N + c) = __floats2half2_rn(v10, v11);
                }
            }
        }
    } else {
        int bat0 = row0 / 1000;
        int cut = (bat0 + 1) * 1000;
        bool has2 = (row0 + 127 >= cut);
        int* outI = (int*)Cf;
#pragma unroll
        for (int ni = 0; ni < 4; ni++) {
            int c = ec + ni * 8;
            float b0 = __ldg(bias + c), b1 = __ldg(bias + c + 1);
            float s00 = 0.f, s01 = 0.f, s10 = 0.f, s11 = 0.f;
#pragma unroll
            for (int mi = 0; mi < 4; mi++) {
                int r = er + mi * 16;
                float v00 = fmaxf(acc[mi][ni][0] + b0, 0.f);
                float v01 = fmaxf(acc[mi][ni][1] + b1, 0.f);
                float v10 = fmaxf(acc[mi][ni][2] + b0, 0.f);
                float v11 = fmaxf(acc[mi][ni][3] + b1, 0.f);
                if (r < cut)     { s00 = fmaxf(s00, v00); s01 = fmaxf(s01, v01); }
                else             { s10 = fmaxf(s10, v00); s11 = fmaxf(s11, v01); }
                if (r + 8 < cut) { s00 = fmaxf(s00, v10); s01 = fmaxf(s01, v11); }
                else             { s10 = fmaxf(s10, v10); s11 = fmaxf(s11, v11); }
            }
#pragma unroll
            for (int d = 4; d <= 16; d <<= 1) {
                s00 = fmaxf(s00, __shfl_xor_sync(0xffffffffu, s00, d));
                s01 = fmaxf(s01, __shfl_xor_sync(0xffffffffu, s01, d));
                s10 = fmaxf(s10, __shfl_xor_sync(0xffffffffu, s10, d));
                s11 = fmaxf(s11, __shfl_xor_sync(0xffffffffu, s11, d));
            }
            if ((lane >> 2) == 0) {
                atomicMax(outI + bat0 * N + c,     __float_as_int(s00));
                atomicMax(outI + bat0 * N + c + 1, __float_as_int(s01));
                if (has2) {
                    atomicMax(outI + (bat0 + 1) * N + c,     __float_as_int(s10));
                    atomicMax(outI + (bat0 + 1) * N + c + 1, __float_as_int(s11));
                }
            }
        }
    }
}

// ---------------- out init ----------------
__global__ void init_out(float* __restrict__ out) {
    int t = blockIdx.x * 256 + threadIdx.x;
    if (t < BATCH * 512) out[t] = 0.f;
}

// ---------------- weight pack (fp32 -> fp16, pad K) ----------------
__global__ void pack_w(const float* __restrict__ w2, const float* __restrict__ pc1,
                       const float* __restrict__ w3, const float* __restrict__ w4,
                       const float* __restrict__ pc2, const float* __restrict__ w5,
                       const float* __restrict__ w6) {
    int t = blockIdx.x * 256 + threadIdx.x;
    if (t >= 742400) return;
    float v;
    if (t < 81920) {
        v = (t < 16384) ? w2[t] : pc1[t - 16384];
    } else if (t < 149504) {
        int i = t - 81920; int r = i / 264, c = i - r * 264;
        v = (c < 259) ? w3[r * 259 + c] : 0.f;
    } else if (t < 247808) {
        v = w4[t - 149504];
    } else if (t < 395264) {
        v = pc2[t - 247808];
    } else if (t < 545792) {
        int i = t - 395264; int r = i / 392, c = i - r * 392;
        v = (c < 387) ? w5[r * 392 - r * 8 + c] : 0.f;  // r*384? no — see below
    } else {
        v = w6[t - 545792];
    }
    g_wH[t] = __float2half_rn(v);
}

// NOTE: the w5 row math above must read w5[r*387+c]; keep explicit correct version:
__global__ void pack_w_fix(const float* __restrict__ w5) {
    int t = blockIdx.x * 256 + threadIdx.x;
    if (t >= 150528) return;               // 384 * 392
    int r = t / 392, c = t - r * 392;
    g_wH[OFF_W5 + t] = __float2half_rn((c < 387) ? w5[r * 387 + c] : 0.f);
}

// ---------------- fused conf + concat + first linear -> fp16 ----------------
__global__ void point_mlp1(const float* __restrict__ x,
                           const float* __restrict__ confW, const float* __restrict__ confb,
                           const float* __restrict__ w1, const float* __restrict__ b1) {
    int t = blockIdx.x * 256 + threadIdx.x;
    if (t >= NROWS * 4) return;
    int p = t >> 2, g = t & 3;
    float x0 = x[p * 3], x1 = x[p * 3 + 1], x2 = x[p * 3 + 2];
    float s = confW[0] * x0 + confW[1] * x1 + confW[2] * x2 + confb[0];
    float conf = 1.f / (1.f + expf(-s));
    const float* wr = w1 + (g * 16) * 4;
    __half h[16];
#pragma unroll
    for (int r = 0; r < 16; r++) {
        float a = __ldg(b1 + g * 16 + r)
                + __ldg(wr + r * 4 + 0) * conf + __ldg(wr + r * 4 + 1) * x0
                + __ldg(wr + r * 4 + 2) * x1   + __ldg(wr + r * 4 + 3) * x2;
        h[r] = __float2half_rn(fmaxf(a, 0.f));
    }
    size_t o = (size_t)p * 64 + g * 16;
    *(uint4*)(g_actP + o)     = *(uint4*)h;
    *(uint4*)(g_actP + o + 8) = *(uint4*)(h + 8);
}

// ---------------- FPS: 4 warps/batch, exact XLA arithmetic, provable early-exit -------------
// Thread tid owns points p = j*128 + tid (j=0..3). Warp-local argmax (bits, min idx), then
// 4-warp combine via parity-double-buffered smem + one barrier. Once the block max min-dist
// is exactly 0 (all points used as centroids), argmax is index 0 forever and dist can never
// change (min(0,d)=0) -> fill remaining outputs with abs0 and exit. Emits ABSOLUTE indices.
__global__ void fps_run(const float* __restrict__ x, const int* __restrict__ far0,
                        int* __restrict__ idxout, int npoint) {
    __shared__ float sxx[512], sxy[512], sxz[512];
    __shared__ unsigned cmb[4][2], cix[4][2];
    int b = blockIdx.x;
    int* out = idxout + b * npoint;
    int abs0 = b * NPT;
    int far = far0[b];
    const float* xb = x + (size_t)b * NPT * 3;
    int tid = threadIdx.x;
    int w = tid >> 5;

    float px[4], py[4], pz[4], dist[4];
#pragma unroll
    for (int j = 0; j < 4; j++) {
        int p = j * 128 + tid;
        if (p < NPT) {
            px[j] = xb[p * 3]; py[j] = xb[p * 3 + 1]; pz[j] = xb[p * 3 + 2];
            dist[j] = 1e10f;
            sxx[p] = px[j]; sxy[p] = py[j]; sxz[p] = pz[j];
        } else {
            px[j] = 0.f; py[j] = 0.f; pz[j] = 0.f;
            dist[j] = -1.0f;   // pad: never selected (valid dists >= 0)
        }
    }
    __syncthreads();

    for (int t = 0; t < npoint; t++) {
        if (tid == 0) out[t] = abs0 + far;
        if (t + 1 == npoint) break;
        float cx = sxx[far], cy = sxy[far], cz = sxz[far];
        float nd[4];
#pragma unroll
        for (int j = 0; j < 4; j++) {         // exact unfused ops: bitwise-match XLA
            float dx = __fsub_rn(px[j], cx);
            float dy = __fsub_rn(py[j], cy);
            float dz = __fsub_rn(pz[j], cz);
            float d  = __fadd_rn(__fadd_rn(__fmul_rn(dx, dx), __fmul_rn(dy, dy)),
                                 __fmul_rn(dz, dz));
            nd[j] = fminf(dist[j], d);
            dist[j] = nd[j];
        }
        float m0 = fmaxf(nd[0], nd[1]), m1 = fmaxf(nd[2], nd[3]);
        float best = fmaxf(m0, m1);
        unsigned mb = __reduce_max_sync(0xffffffffu, __float_as_uint(best));
        unsigned c[4];
#pragma unroll
        for (int j = 0; j < 4; j++)
            c[j] = (__float_as_uint(nd[j]) == mb) ? (unsigned)(j * 128 + tid) : 0xffffffffu;
        unsigned cw = __reduce_min_sync(0xffffffffu, min(min(c[0], c[1]), min(c[2], c[3])));
        int sl = t & 1;
        if ((tid & 31) == 0) { cmb[w][sl] = mb; cix[w][sl] = cw; }
        __syncthreads();
        unsigned q0 = cmb[0][sl], q1 = cmb[1][sl], q2 = cmb[2][sl], q3 = cmb[3][sl];
        unsigned fm = max(max(q0, q1), max(q2, q3));
        unsigned i0 = (q0 == fm) ? cix[0][sl] : 0xffffffffu;
        unsigned i1 = (q1 == fm) ? cix[1][sl] : 0xffffffffu;
        unsigned i2 = (q2 == fm) ? cix[2][sl] : 0xffffffffu;
        unsigned i3 = (q3 == fm) ? cix[3][sl] : 0xffffffffu;
        far = (int)min(min(i0, i1), min(i2, i3));
        if (fm == 0u) {
            // all dists exactly 0: every future selection is point 0 of this batch
            for (int q = t + 1 + tid; q < npoint; q += 128) out[q] = abs0;
            break;
        }
    }
}

// ---------------- tail builder: tail[r] = [x(idx[r]).xyz as fp16, 0 x5] ----------------
__global__ void make_tail(const float* __restrict__ x, const int* __restrict__ idx,
                          __half* __restrict__ tail, int n) {
    int r = blockIdx.x * 256 + threadIdx.x;
    if (r >= n) return;
    const float* xp = x + (size_t)idx[r] * 3;
    __half h[8];
#pragma unroll
    for (int j = 0; j < 8; j++) h[j] = __float2half(0.f);
#pragma unroll
    for (int j = 0; j < 3; j++) h[j] = __float2half_rn(xp[j]);
    *(uint4*)(tail + (size_t)r * 8) = *(uint4*)h;
}

// ---------------- launch ----------------
extern "C" void kernel_launch(void* const* d_in, const int* in_sizes, int n_in,
                              void* d_out, int out_size) {
    const float* x     = (const float*)d_in[0];
    const float* confW = (const float*)d_in[1];
    const float* confb = (const float*)d_in[2];
    const float* w1    = (const float*)d_in[3];
    const float* b1    = (const float*)d_in[4];
    const float* w2    = (const float*)d_in[5];
    const float* b2    = (const float*)d_in[6];
    const float* pc1W  = (const float*)d_in[7];
    const float* pc1b  = (const float*)d_in[8];
    const float* w3    = (const float*)d_in[9];
    const float* b3    = (const float*)d_in[10];
    const float* w4    = (const float*)d_in[11];
    const float* b4    = (const float*)d_in[12];
    const float* pc2W  = (const float*)d_in[13];
    const float* pc2b  = (const float*)d_in[14];
    const float* w5    = (const float*)d_in[15];
    const float* b5    = (const float*)d_in[16];
    const float* w6    = (const float*)d_in[17];
    const float* b6    = (const float*)d_in[18];
    const int* far1    = (const int*)d_in[20];
    const int* far2    = (const int*)d_in[21];
    float* out = (float*)d_out;

    __half *actP, *actQ, *wH, *tail1, *tail2;
    int *idx1, *idx2;
    cudaGetSymbolAddress((void**)&actP, g_actP);
    cudaGetSymbolAddress((void**)&actQ, g_actQ);
    cudaGetSymbolAddress((void**)&wH,   g_wH);
    cudaGetSymbolAddress((void**)&tail1, g_tail1);
    cudaGetSymbolAddress((void**)&tail2, g_tail2);
    cudaGetSymbolAddress((void**)&idx1, g_idx1);
    cudaGetSymbolAddress((void**)&idx2, g_idx2);

    cudaFuncSetAttribute(gemm_f16, cudaFuncAttributeMaxDynamicSharedMemorySize, GEMM_SMEM);

    static cudaStream_t s1 = nullptr, s2 = nullptr;
    static cudaEvent_t evA = nullptr, ev1 = nullptr, ev2 = nullptr;
    if (s1 == nullptr) {
        cudaStreamCreateWithFlags(&s1, cudaStreamNonBlocking);
        cudaStreamCreateWithFlags(&s2, cudaStreamNonBlocking);
        cudaEventCreateWithFlags(&evA, cudaEventDisableTiming);
        cudaEventCreateWithFlags(&ev1, cudaEventDisableTiming);
        cudaEventCreateWithFlags(&ev2, cudaEventDisableTiming);
    }

    init_out<<<(BATCH * 512 + 255) / 256, 256>>>(out);

    // fork: FPS1+tail1 on s1, FPS2+tail2 on s2
    cudaEventRecord(evA, 0);
    cudaStreamWaitEvent(s1, evA, 0);
    cudaStreamWaitEvent(s2, evA, 0);
    fps_run<<<BATCH, 128, 0, s1>>>(x, far1, idx1, 500);
    make_tail<<<(NROWS + 255) / 256, 256, 0, s1>>>(x, idx1, tail1, NROWS);
    cudaEventRecord(ev1, s1);
    fps_run<<<BATCH, 128, 0, s2>>>(x, far2, idx2, 1000);
    make_tail<<<(128000 + 255) / 256, 256, 0, s2>>>(x, idx2, tail2, 128000);
    cudaEventRecord(ev2, s2);

    pack_w<<<(742400 + 255) / 256, 256>>>(w2, pc1W, w3, w4, pc2W, w5, w6);
    pack_w_fix<<<(150528 + 255) / 256, 256>>>(w5);
    point_mlp1<<<(NROWS * 4 + 255) / 256, 256>>>(x, confW, confb, w1, b1);

    // l2: (64000x256, K=64), relu        actP -> actQ
    gemm_f16<<<dim3(2, 500), 256, GEMM_SMEM>>>(actP, wH + OFF_W2, b2,
        nullptr, actQ, nullptr, nullptr, NROWS, 256, 64, 64, 1, 1);
    // l3: (64000x256, K=256)             actQ -> actP
    gemm_f16<<<dim3(2, 500), 256, GEMM_SMEM>>>(actQ, wH + OFF_PC1, pc1b,
        nullptr, actP, nullptr, nullptr, NROWS, 256, 256, 256, 0, 1);

    // join idx1; l4 inline-gathers A rows from l3 output (lda=256, K=264 w/ tail)
    cudaStreamWaitEvent(0, ev1, 0);
    gemm_f16<<<dim3(2, 500), 256, GEMM_SMEM>>>(actP, wH + OFF_W3, b3,
        nullptr, actQ, idx1, tail1, NROWS, 256, 264, 256, 1, 1);
    // l5: (64000x384, K=256), relu       actQ -> actP
    gemm_f16<<<dim3(3, 500), 256, GEMM_SMEM>>>(actQ, wH + OFF_W4, b4,
        nullptr, actP, nullptr, nullptr, NROWS, 384, 256, 256, 1, 1);
    // l6: (64000x384, K=384)             actP -> actQ
    gemm_f16<<<dim3(3, 500), 256, GEMM_SMEM>>>(actP, wH + OFF_PC2, pc2b,
        nullptr, actQ, nullptr, nullptr, NROWS, 384, 384, 384, 0, 1);

    // join idx2; l7 inline-gathers A rows from l6 output (lda=384, K=392 w/ tail)
    cudaStreamWaitEvent(0, ev2, 0);
    gemm_f16<<<dim3(3, 1000), 256, GEMM_SMEM>>>(actQ, wH + OFF_W5, b5,
        nullptr, actP, idx2, tail2, 128000, 384, 392, 384, 1, 1);
    // l8: (128000x512, K=384), relu, FUSED max-pool -> out
    gemm_f16<<<dim3(4, 1000), 256, GEMM_SMEM>>>(actP, wH + OFF_W6, b6,
        out, nullptr, nullptr, nullptr, 128000, 512, 384, 384, 1, 2);
}

// round 12
// speedup vs baseline: 1.7153x; 1.2419x over previous
#include <cuda_runtime.h>
#include <cuda_fp16.h>
#include <math.h>
#include <cstdint>

#define BATCH 128
#define NPT   500
#define NROWS (BATCH*NPT)

typedef unsigned long long ull;

// ---------------- scratch (static; no allocation) ----------------
__device__ __align__(256) __half g_actP[52428800];
__device__ __align__(256) __half g_actQ[52428800];
__device__ __align__(256) __half g_wH[742528];
__device__ __align__(256) __half g_tailX[NROWS * 8];   // [x.xyz fp16, 0 x5] natural order
__device__ __align__(256) int g_idx1[BATCH * 500];
__device__ __align__(256) int g_idx2[BATCH * 1000];
__device__ __align__(256) unsigned g_mask[2048];       // 64000-bit idx2 membership bitmap

// weight arena offsets (elements, K padded to mult of 8)
#define OFF_W2   0
#define OFF_PC1  16384
#define OFF_W3   81920
#define OFF_W4   149504
#define OFF_PC2  247808
#define OFF_W5   395264
#define OFF_W6   545792

// ---------------- helpers ----------------
__device__ __forceinline__ uint32_t smem_u32(const void* p) {
    uint32_t a;
    asm("{ .reg .u64 t; cvta.to.shared.u64 t, %1; cvt.u32.u64 %0, t; }" : "=r"(a) : "l"(p));
    return a;
}
__device__ __forceinline__ void cpa16(uint32_t dst, const void* src, int sz) {
    asm volatile("cp.async.cg.shared.global [%0], [%1], 16, %2;"
        :: "r"(dst), "l"(src), "r"(sz) : "memory");
}
__device__ __forceinline__ void ldm_x4(uint32_t* r, uint32_t addr) {
    asm volatile("ldmatrix.sync.aligned.m8n8.x4.shared.b16 {%0,%1,%2,%3}, [%4];"
        : "=r"(r[0]), "=r"(r[1]), "=r"(r[2]), "=r"(r[3]) : "r"(addr));
}
__device__ __forceinline__ void mma_f16(float* d, const uint32_t* a, uint32_t b0, uint32_t b1) {
    asm volatile("mma.sync.aligned.m16n8k16.row.col.f32.f16.f16.f32 "
        "{%0,%1,%2,%3}, {%4,%5,%6,%7}, {%8,%9}, {%0,%1,%2,%3};"
        : "+f"(d[0]), "+f"(d[1]), "+f"(d[2]), "+f"(d[3])
        : "r"(a[0]), "r"(a[1]), "r"(a[2]), "r"(a[3]), "r"(b0), "r"(b1));
}

// ---------------- fp16 HMMA GEMM (BN=128 tile; optional row-gather; optional x-tail) --------
// C = relu?( sum_k A[m,k]*W[n,k] + bias[n] ). CTA 128x128x64, 8 warps 2Mx4N, warp 64x32.
// 3-stage cp.async (32KB/stage), 2 CTAs/SM. rowIdx: absolute A rows (smem-cached).
// tailA (if set): source for K columns >= lda, indexed by OUTPUT row (natural order).
// mode: 0 fp32 C, 1 fp16 C, 2 fused masked per-500-row-batch column max into Cf.
#define NSTG 3
#define STG 32768
static const int GEMM_SMEM = NSTG * STG + 512;

__device__ __forceinline__ void g_fill(
    const __half* __restrict__ A, const __half* __restrict__ W,
    const int* __restrict__ sIdx, int useIdx, const __half* __restrict__ tailA,
    int K, int lda, int row0, int col0, int s, int nst, uint32_t sb, int tid)
{
    if (s < nst) {
        int k0 = s << 6;
        uint32_t base = sb + (uint32_t)(s % NSTG) * STG;
#pragma unroll
        for (int i = 0; i < 4; i++) {
            int g = (i << 8) + tid;
            int r = g >> 3, c = g & 7;
            int kg = k0 + (c << 3);
            int ok = (kg < K) ? 16 : 0;
            uint32_t d = base + ((uint32_t)r << 7) + (((uint32_t)(c ^ (r & 7))) << 4);
            int srcRow = useIdx ? sIdx[r] : (row0 + r);
            const __half* srcA;
            if (tailA != nullptr && kg >= lda)
                srcA = tailA + (size_t)(row0 + r) * 8 + (kg - lda);
            else
                srcA = A + (size_t)srcRow * lda + kg;
            cpa16(d,         srcA, ok);
            cpa16(d + 16384, W + (size_t)(col0 + r) * K + kg, ok);
        }
    }
    asm volatile("cp.async.commit_group;" ::: "memory");
}

__global__ void __launch_bounds__(256, 2)
gemm_f16(const __half* __restrict__ A, const __half* __restrict__ W,
         const float* __restrict__ bias,
         float* __restrict__ Cf, __half* __restrict__ Ch,
         const int* __restrict__ rowIdx, const __half* __restrict__ tailA,
         const unsigned* __restrict__ maskp,
         int M, int N, int K, int lda, int relu, int mode)
{
    extern __shared__ char smem[];
    int* sIdx = (int*)(smem + NSTG * STG);
    uint32_t sb = smem_u32(smem);
    int tid = threadIdx.x, lane = tid & 31, wid = tid >> 5;
    int warp_m = wid & 1;
    int warp_n = wid >> 1;
    int row0 = blockIdx.y << 7;
    int col0 = blockIdx.x << 7;
    int nst = (K + 63) >> 6;
    int useIdx = (rowIdx != nullptr);

    if (useIdx && tid < 128) sIdx[tid] = rowIdx[row0 + tid];
    __syncthreads();

    float acc[4][4][4];
#pragma unroll
    for (int a = 0; a < 4; a++)
#pragma unroll
        for (int b = 0; b < 4; b++)
#pragma unroll
            for (int c = 0; c < 4; c++) acc[a][b][c] = 0.f;

    g_fill(A, W, sIdx, useIdx, tailA, K, lda, row0, col0, 0, nst, sb, tid);
    g_fill(A, W, sIdx, useIdx, tailA, K, lda, row0, col0, 1, nst, sb, tid);

    int a_row = warp_m * 64 + (lane & 15);
    int a_sel = lane >> 4;
    int b_row4 = warp_n * 32 + ((lane >> 4) << 3) + (lane & 7);
    int b_ksel = (lane >> 3) & 1;

    for (int s = 0; s < nst; s++) {
        asm volatile("cp.async.wait_group 1;" ::: "memory");
        __syncthreads();
        uint32_t base = sb + (uint32_t)(s % NSTG) * STG;
        int kr = K - (s << 6);
        int kcnt = (kr + 15) >> 4; if (kcnt > 4) kcnt = 4;
        for (int ks = 0; ks < kcnt; ks++) {
            uint32_t Fa[4][4];
            int ch_a = (ks << 1) + a_sel;
#pragma unroll
            for (int mi = 0; mi < 4; mi++) {
                int rr = a_row + mi * 16;
                ldm_x4(Fa[mi], base + ((uint32_t)rr << 7) + (((uint32_t)(ch_a ^ (rr & 7))) << 4));
            }
            int ch_b = (ks << 1) + b_ksel;
#pragma unroll
            for (int np = 0; np < 2; np++) {
                int nr = b_row4 + np * 16;
                uint32_t B4[4];
                ldm_x4(B4, base + 16384 + ((uint32_t)nr << 7)
                           + (((uint32_t)(ch_b ^ (nr & 7))) << 4));
#pragma unroll
                for (int mi = 0; mi < 4; mi++) {
                    mma_f16(acc[mi][np * 2],     Fa[mi], B4[0], B4[1]);
                    mma_f16(acc[mi][np * 2 + 1], Fa[mi], B4[2], B4[3]);
                }
            }
        }
        g_fill(A, W, sIdx, useIdx, tailA, K, lda, row0, col0, s + 2, nst, sb, tid);
    }

    int er = row0 + warp_m * 64 + (lane >> 2);
    int ec = col0 + warp_n * 32 + ((lane & 3) << 1);
    if (mode != 2) {
#pragma unroll
        for (int ni = 0; ni < 4; ni++) {
            int c = ec + ni * 8;
            float b0 = __ldg(bias + c), b1 = __ldg(bias + c + 1);
#pragma unroll
            for (int mi = 0; mi < 4; mi++) {
                int r = er + mi * 16;
                float v00 = acc[mi][ni][0] + b0, v01 = acc[mi][ni][1] + b1;
                float v10 = acc[mi][ni][2] + b0, v11 = acc[mi][ni][3] + b1;
                if (relu) {
                    v00 = fmaxf(v00, 0.f); v01 = fmaxf(v01, 0.f);
                    v10 = fmaxf(v10, 0.f); v11 = fmaxf(v11, 0.f);
                }
                if (mode == 0) {
                    *(float2*)(Cf + (size_t)r * N + c)       = make_float2(v00, v01);
                    *(float2*)(Cf + (size_t)(r + 8) * N + c) = make_float2(v10, v11);
                } else {
                    *(__half2*)(Ch + (size_t)r * N + c)       = __floats2half2_rn(v00, v01);
                    *(__half2*)(Ch + (size_t)(r + 8) * N + c) = __floats2half2_rn(v10, v11);
                }
            }
        }
    } else {
        // masked per-batch (500 rows) column max -> Cf[batch][N] via atomicMax.
        // Row r contributes only if bit r of maskp is set (r in idx2's support set).
        // All values relu'd (>=0): 0 is the identity, int compare == float compare.
        int bat0 = row0 / 500;
        int cut = (bat0 + 1) * 500;
        bool has2 = (row0 + 127 >= cut);
        int* outI = (int*)Cf;
        // per-thread row-inclusion flags (8 rows: er+mi*16, er+mi*16+8)
        float inc[8];
#pragma unroll
        for (int mi = 0; mi < 4; mi++) {
            int ra = er + mi * 16, rb = ra + 8;
            inc[mi * 2]     = ((maskp[ra >> 5] >> (ra & 31)) & 1u) ? 1.f : 0.f;
            inc[mi * 2 + 1] = ((maskp[rb >> 5] >> (rb & 31)) & 1u) ? 1.f : 0.f;
        }
#pragma unroll
        for (int ni = 0; ni < 4; ni++) {
            int c = ec + ni * 8;
            float b0 = __ldg(bias + c), b1 = __ldg(bias + c + 1);
            float s00 = 0.f, s01 = 0.f, s10 = 0.f, s11 = 0.f;
#pragma unroll
            for (int mi = 0; mi < 4; mi++) {
                int r = er + mi * 16;
                float v00 = fmaxf(acc[mi][ni][0] + b0, 0.f) * inc[mi * 2];
                float v01 = fmaxf(acc[mi][ni][1] + b1, 0.f) * inc[mi * 2];
                float v10 = fmaxf(acc[mi][ni][2] + b0, 0.f) * inc[mi * 2 + 1];
                float v11 = fmaxf(acc[mi][ni][3] + b1, 0.f) * inc[mi * 2 + 1];
                if (r < cut)     { s00 = fmaxf(s00, v00); s01 = fmaxf(s01, v01); }
                else             { s10 = fmaxf(s10, v00); s11 = fmaxf(s11, v01); }
                if (r + 8 < cut) { s00 = fmaxf(s00, v10); s01 = fmaxf(s01, v11); }
                else             { s10 = fmaxf(s10, v10); s11 = fmaxf(s11, v11); }
            }
#pragma unroll
            for (int d = 4; d <= 16; d <<= 1) {
                s00 = fmaxf(s00, __shfl_xor_sync(0xffffffffu, s00, d));
                s01 = fmaxf(s01, __shfl_xor_sync(0xffffffffu, s01, d));
                s10 = fmaxf(s10, __shfl_xor_sync(0xffffffffu, s10, d));
                s11 = fmaxf(s11, __shfl_xor_sync(0xffffffffu, s11, d));
            }
            if ((lane >> 2) == 0) {
                atomicMax(outI + bat0 * N + c,     __float_as_int(s00));
                atomicMax(outI + bat0 * N + c + 1, __float_as_int(s01));
                if (has2) {
                    atomicMax(outI + (bat0 + 1) * N + c,     __float_as_int(s10));
                    atomicMax(outI + (bat0 + 1) * N + c + 1, __float_as_int(s11));
                }
            }
        }
    }
}

// ---------------- out init ----------------
__global__ void init_out(float* __restrict__ out) {
    int t = blockIdx.x * 256 + threadIdx.x;
    if (t < BATCH * 512) out[t] = 0.f;
}

// ---------------- mask init + build (idx2 support bitmap over 64000 positions) ----------------
__global__ void init_mask() {
    int t = blockIdx.x * 256 + threadIdx.x;
    if (t < 2048) g_mask[t] = 0u;
}
__global__ void build_mask(const int* __restrict__ idx2) {
    int t = blockIdx.x * 256 + threadIdx.x;
    if (t >= BATCH * 1000) return;
    int v = idx2[t];
    atomicOr(&g_mask[v >> 5], 1u << (v & 31));
}

// ---------------- weight pack (fp32 -> fp16, pad K) ----------------
__global__ void pack_w(const float* __restrict__ w2, const float* __restrict__ pc1,
                       const float* __restrict__ w3, const float* __restrict__ w4,
                       const float* __restrict__ pc2, const float* __restrict__ w5,
                       const float* __restrict__ w6) {
    int t = blockIdx.x * 256 + threadIdx.x;
    if (t >= 742400) return;
    float v;
    if (t < 81920) {
        v = (t < 16384) ? w2[t] : pc1[t - 16384];
    } else if (t < 149504) {
        int i = t - 81920; int r = i / 264, c = i - r * 264;
        v = (c < 259) ? w3[r * 259 + c] : 0.f;
    } else if (t < 247808) {
        v = w4[t - 149504];
    } else if (t < 395264) {
        v = pc2[t - 247808];
    } else if (t < 545792) {
        int i = t - 395264; int r = i / 392, c = i - r * 392;
        v = (c < 387) ? w5[r * 387 + c] : 0.f;
    } else {
        v = w6[t - 545792];
    }
    g_wH[t] = __float2half_rn(v);
}

// ---------------- fused conf + concat + first linear -> fp16 ----------------
__global__ void point_mlp1(const float* __restrict__ x,
                           const float* __restrict__ confW, const float* __restrict__ confb,
                           const float* __restrict__ w1, const float* __restrict__ b1) {
    int t = blockIdx.x * 256 + threadIdx.x;
    if (t >= NROWS * 4) return;
    int p = t >> 2, g = t & 3;
    float x0 = x[p * 3], x1 = x[p * 3 + 1], x2 = x[p * 3 + 2];
    float s = confW[0] * x0 + confW[1] * x1 + confW[2] * x2 + confb[0];
    float conf = 1.f / (1.f + expf(-s));
    const float* wr = w1 + (g * 16) * 4;
    __half h[16];
#pragma unroll
    for (int r = 0; r < 16; r++) {
        float a = __ldg(b1 + g * 16 + r)
                + __ldg(wr + r * 4 + 0) * conf + __ldg(wr + r * 4 + 1) * x0
                + __ldg(wr + r * 4 + 2) * x1   + __ldg(wr + r * 4 + 3) * x2;
        h[r] = __float2half_rn(fmaxf(a, 0.f));
    }
    size_t o = (size_t)p * 64 + g * 16;
    *(uint4*)(g_actP + o)     = *(uint4*)h;
    *(uint4*)(g_actP + o + 8) = *(uint4*)(h + 8);
}

// ---------------- natural-order x tail: tailX[r] = [x[r].xyz fp16, 0 x5] ----------------
__global__ void make_tailx(const float* __restrict__ x) {
    int r = blockIdx.x * 256 + threadIdx.x;
    if (r >= NROWS) return;
    const float* xp = x + (size_t)r * 3;
    __half h[8];
#pragma unroll
    for (int j = 0; j < 8; j++) h[j] = __float2half(0.f);
#pragma unroll
    for (int j = 0; j < 3; j++) h[j] = __float2half_rn(xp[j]);
    *(uint4*)(g_tailX + (size_t)r * 8) = *(uint4*)h;
}

// ---------------- FPS: 4 warps/batch, exact XLA arithmetic, provable early-exit -------------
__global__ void fps_run(const float* __restrict__ x, const int* __restrict__ far0,
                        int* __restrict__ idxout, int npoint) {
    __shared__ float sxx[512], sxy[512], sxz[512];
    __shared__ unsigned cmb[4][2], cix[4][2];
    int b = blockIdx.x;
    int* out = idxout + b * npoint;
    int abs0 = b * NPT;
    int far = far0[b];
    const float* xb = x + (size_t)b * NPT * 3;
    int tid = threadIdx.x;
    int w = tid >> 5;

    float px[4], py[4], pz[4], dist[4];
#pragma unroll
    for (int j = 0; j < 4; j++) {
        int p = j * 128 + tid;
        if (p < NPT) {
            px[j] = xb[p * 3]; py[j] = xb[p * 3 + 1]; pz[j] = xb[p * 3 + 2];
            dist[j] = 1e10f;
            sxx[p] = px[j]; sxy[p] = py[j]; sxz[p] = pz[j];
        } else {
            px[j] = 0.f; py[j] = 0.f; pz[j] = 0.f;
            dist[j] = -1.0f;
        }
    }
    __syncthreads();

    for (int t = 0; t < npoint; t++) {
        if (tid == 0) out[t] = abs0 + far;
        if (t + 1 == npoint) break;
        float cx = sxx[far], cy = sxy[far], cz = sxz[far];
        float nd[4];
#pragma unroll
        for (int j = 0; j < 4; j++) {
            float dx = __fsub_rn(px[j], cx);
            float dy = __fsub_rn(py[j], cy);
            float dz = __fsub_rn(pz[j], cz);
            float d  = __fadd_rn(__fadd_rn(__fmul_rn(dx, dx), __fmul_rn(dy, dy)),
                                 __fmul_rn(dz, dz));
            nd[j] = fminf(dist[j], d);
            dist[j] = nd[j];
        }
        float m0 = fmaxf(nd[0], nd[1]), m1 = fmaxf(nd[2], nd[3]);
        float best = fmaxf(m0, m1);
        unsigned mb = __reduce_max_sync(0xffffffffu, __float_as_uint(best));
        unsigned c[4];
#pragma unroll
        for (int j = 0; j < 4; j++)
            c[j] = (__float_as_uint(nd[j]) == mb) ? (unsigned)(j * 128 + tid) : 0xffffffffu;
        unsigned cw = __reduce_min_sync(0xffffffffu, min(min(c[0], c[1]), min(c[2], c[3])));
        int sl = t & 1;
        if ((tid & 31) == 0) { cmb[w][sl] = mb; cix[w][sl] = cw; }
        __syncthreads();
        unsigned q0 = cmb[0][sl], q1 = cmb[1][sl], q2 = cmb[2][sl], q3 = cmb[3][sl];
        unsigned fm = max(max(q0, q1), max(q2, q3));
        unsigned i0 = (q0 == fm) ? cix[0][sl] : 0xffffffffu;
        unsigned i1 = (q1 == fm) ? cix[1][sl] : 0xffffffffu;
        unsigned i2 = (q2 == fm) ? cix[2][sl] : 0xffffffffu;
        unsigned i3 = (q3 == fm) ? cix[3][sl] : 0xffffffffu;
        far = (int)min(min(i0, i1), min(i2, i3));
        if (fm == 0u) {
            for (int q = t + 1 + tid; q < npoint; q += 128) out[q] = abs0;
            break;
        }
    }
}

// ---------------- launch ----------------
extern "C" void kernel_launch(void* const* d_in, const int* in_sizes, int n_in,
                              void* d_out, int out_size) {
    const float* x     = (const float*)d_in[0];
    const float* confW = (const float*)d_in[1];
    const float* confb = (const float*)d_in[2];
    const float* w1    = (const float*)d_in[3];
    const float* b1    = (const float*)d_in[4];
    const float* w2    = (const float*)d_in[5];
    const float* b2    = (const float*)d_in[6];
    const float* pc1W  = (const float*)d_in[7];
    const float* pc1b  = (const float*)d_in[8];
    const float* w3    = (const float*)d_in[9];
    const float* b3    = (const float*)d_in[10];
    const float* w4    = (const float*)d_in[11];
    const float* b4    = (const float*)d_in[12];
    const float* pc2W  = (const float*)d_in[13];
    const float* pc2b  = (const float*)d_in[14];
    const float* w5    = (const float*)d_in[15];
    const float* b5    = (const float*)d_in[16];
    const float* w6    = (const float*)d_in[17];
    const float* b6    = (const float*)d_in[18];
    const int* far1    = (const int*)d_in[20];
    const int* far2    = (const int*)d_in[21];
    float* out = (float*)d_out;

    __half *actP, *actQ, *wH, *tailX;
    int *idx1, *idx2;
    unsigned* maskp;
    cudaGetSymbolAddress((void**)&actP, g_actP);
    cudaGetSymbolAddress((void**)&actQ, g_actQ);
    cudaGetSymbolAddress((void**)&wH,   g_wH);
    cudaGetSymbolAddress((void**)&tailX, g_tailX);
    cudaGetSymbolAddress((void**)&idx1, g_idx1);
    cudaGetSymbolAddress((void**)&idx2, g_idx2);
    cudaGetSymbolAddress((void**)&maskp, g_mask);

    cudaFuncSetAttribute(gemm_f16, cudaFuncAttributeMaxDynamicSharedMemorySize, GEMM_SMEM);

    static cudaStream_t s1 = nullptr, s2 = nullptr;
    static cudaEvent_t evA = nullptr, ev1 = nullptr, ev2 = nullptr;
    if (s1 == nullptr) {
        cudaStreamCreateWithFlags(&s1, cudaStreamNonBlocking);
        cudaStreamCreateWithFlags(&s2, cudaStreamNonBlocking);
        cudaEventCreateWithFlags(&evA, cudaEventDisableTiming);
        cudaEventCreateWithFlags(&ev1, cudaEventDisableTiming);
        cudaEventCreateWithFlags(&ev2, cudaEventDisableTiming);
    }

    init_out<<<(BATCH * 512 + 255) / 256, 256>>>(out);

    // fork: FPS1 on s1; FPS2 + membership bitmap on s2
    cudaEventRecord(evA, 0);
    cudaStreamWaitEvent(s1, evA, 0);
    cudaStreamWaitEvent(s2, evA, 0);
    fps_run<<<BATCH, 128, 0, s1>>>(x, far1, idx1, 500);
    cudaEventRecord(ev1, s1);
    init_mask<<<8, 256, 0, s2>>>();
    fps_run<<<BATCH, 128, 0, s2>>>(x, far2, idx2, 1000);
    build_mask<<<(BATCH * 1000 + 255) / 256, 256, 0, s2>>>(idx2);
    cudaEventRecord(ev2, s2);

    pack_w<<<(742400 + 255) / 256, 256>>>(w2, pc1W, w3, w4, pc2W, w5, w6);
    make_tailx<<<(NROWS + 255) / 256, 256>>>(x);
    point_mlp1<<<(NROWS * 4 + 255) / 256, 256>>>(x, confW, confb, w1, b1);

    // l2: (64000x256, K=64), relu        actP -> actQ
    gemm_f16<<<dim3(2, 500), 256, GEMM_SMEM>>>(actP, wH + OFF_W2, b2,
        nullptr, actQ, nullptr, nullptr, nullptr, NROWS, 256, 64, 64, 1, 1);
    // l3: (64000x256, K=256)             actQ -> actP
    gemm_f16<<<dim3(2, 500), 256, GEMM_SMEM>>>(actQ, wH + OFF_PC1, pc1b,
        nullptr, actP, nullptr, nullptr, nullptr, NROWS, 256, 256, 256, 0, 1);
    // l4' (natural point order): A = l3 + x-tail, K=264, relu    actP -> actQ
    gemm_f16<<<dim3(2, 500), 256, GEMM_SMEM>>>(actP, wH + OFF_W3, b3,
        nullptr, actQ, nullptr, tailX, nullptr, NROWS, 256, 264, 256, 1, 1);
    // l5': (64000x384, K=256), relu      actQ -> actP
    gemm_f16<<<dim3(3, 500), 256, GEMM_SMEM>>>(actQ, wH + OFF_W4, b4,
        nullptr, actP, nullptr, nullptr, nullptr, NROWS, 384, 256, 256, 1, 1);
    // l6': (64000x384, K=384)            actP -> actQ
    gemm_f16<<<dim3(3, 500), 256, GEMM_SMEM>>>(actP, wH + OFF_PC2, pc2b,
        nullptr, actQ, nullptr, nullptr, nullptr, NROWS, 384, 384, 384, 0, 1);

    // join idx1; l7 over 64000 POSITIONS: A row j = l6'[idx1[j]], tail = x[j] natural
    cudaStreamWaitEvent(0, ev1, 0);
    gemm_f16<<<dim3(3, 500), 256, GEMM_SMEM>>>(actQ, wH + OFF_W5, b5,
        nullptr, actP, idx1, tailX, nullptr, NROWS, 384, 392, 384, 1, 1);

    // join idx2 bitmap; l8 over 64000 positions, masked fused max-pool -> out
    cudaStreamWaitEvent(0, ev2, 0);
    gemm_f16<<<dim3(4, 500), 256, GEMM_SMEM>>>(actP, wH + OFF_W6, b6,
        out, nullptr, nullptr, nullptr, maskp, NROWS, 512, 384, 384, 1, 2);
}